// round 7
// baseline (speedup 1.0000x reference)
#include <cuda_runtime.h>
#include <math.h>

// Problem constants (fixed by the reference: B=8, N=8192, D=3)
#define BATCH   8
#define NPTS    8192
#define TOTAL   (BATCH * NPTS)        // 65536
#define G       32                    // grid cells per axis
#define NC      (G * G * G)           // 32768 cells per batch
#define GRID_LO (-4.5f)
#define CELL_H  (0.28125f)            // 9.0 / 32
#define INV_H   (1.0f / CELL_H)

// Static scratch (no device allocation allowed).
__device__ int    g_cnt_ori[BATCH * NC];
__device__ int    g_off_ori[BATCH * NC];
__device__ int    g_cur_ori[BATCH * NC];
__device__ int    g_cnt_adv[BATCH * NC];
__device__ int    g_off_adv[BATCH * NC];
__device__ int    g_cur_adv[BATCH * NC];
__device__ float4 g_sorted_ori[TOTAL];   // (x, y, z, 0.5*||o||^2)
__device__ float4 g_sorted_adv[TOTAL];   // (x, y, z, ||a||^2)
__device__ int    g_adv_orig[TOTAL];     // original index within batch
__device__ float  g_res[TOTAL];          // per-query nearest dist^2, original order

__device__ __forceinline__ int cell1(float v) {
    int c = (int)floorf((v - GRID_LO) * INV_H);
    return min(G - 1, max(0, c));
}

// ---------------------------------------------------------------- zero
__global__ void k_zero() {
    int i = blockIdx.x * blockDim.x + threadIdx.x;
    int stride = gridDim.x * blockDim.x;
    for (; i < BATCH * NC; i += stride) { g_cnt_ori[i] = 0; g_cnt_adv[i] = 0; }
}

// ---------------------------------------------------------------- count
// threads [0, TOTAL) -> ori points, [TOTAL, 2*TOTAL) -> adv points
__global__ void k_count(const float* __restrict__ ori, const float* __restrict__ adv) {
    int t = blockIdx.x * blockDim.x + threadIdx.x;
    bool is_ori = t < TOTAL;
    int idx = is_ori ? t : t - TOTAL;
    int b = idx >> 13, i = idx & (NPTS - 1);
    const float* p = (is_ori ? ori : adv) + ((size_t)b * NPTS + i) * 3;
    int ci = (cell1(p[2]) * G + cell1(p[1])) * G + cell1(p[0]);
    atomicAdd((is_ori ? g_cnt_ori : g_cnt_adv) + b * NC + ci, 1);
}

// ---------------------------------------------------------------- scan
// 16 blocks: blockIdx 0..7 = ori batch b, 8..15 = adv batch b. 1024 threads.
__global__ void k_scan() {
    __shared__ int s[1024];
    int kind = blockIdx.x >> 3, b = blockIdx.x & 7, t = threadIdx.x;
    int* cnt = (kind ? g_cnt_adv : g_cnt_ori) + b * NC;
    int* off = (kind ? g_off_adv : g_off_ori) + b * NC;
    int* cur = (kind ? g_cur_adv : g_cur_ori) + b * NC;
    const int CH = NC / 1024;   // 32 cells per thread, exact
    int base = t * CH;
    int local = 0;
#pragma unroll
    for (int j = 0; j < CH; j++) local += cnt[base + j];
    s[t] = local;
    __syncthreads();
    for (int d = 1; d < 1024; d <<= 1) {
        int v = (t >= d) ? s[t - d] : 0;
        __syncthreads();
        s[t] += v;
        __syncthreads();
    }
    int run = s[t] - local;   // exclusive prefix of this chunk
    for (int j = 0; j < CH; j++) {
        off[base + j] = run;
        cur[base + j] = run;
        run += cnt[base + j];
    }
}

// ---------------------------------------------------------------- scatter
__global__ void k_scatter(const float* __restrict__ ori, const float* __restrict__ adv) {
    int t = blockIdx.x * blockDim.x + threadIdx.x;
    bool is_ori = t < TOTAL;
    int idx = is_ori ? t : t - TOTAL;
    int b = idx >> 13, i = idx & (NPTS - 1);
    const float* p = (is_ori ? ori : adv) + ((size_t)b * NPTS + i) * 3;
    float x = p[0], y = p[1], z = p[2];
    int ci = (cell1(z) * G + cell1(y)) * G + cell1(x);
    if (is_ori) {
        int pos = atomicAdd(&g_cur_ori[b * NC + ci], 1);
        g_sorted_ori[b * NPTS + pos] = make_float4(x, y, z, 0.5f * (x * x + y * y + z * z));
    } else {
        int pos = atomicAdd(&g_cur_adv[b * NC + ci], 1);
        g_sorted_adv[b * NPTS + pos] = make_float4(x, y, z, x * x + y * y + z * z);
        g_adv_orig[b * NPTS + pos] = i;
    }
}

// ---------------------------------------------------------------- query
// Each thread: one sorted adv point. Expanding Chebyshev rings with exact
// box-distance pruning; termination when best <= (dist to nearest unsearched
// face)^2. Result is the exact min (same fp formula as brute force).
__global__ __launch_bounds__(128) void k_query() {
    int slot = blockIdx.x * 128 + threadIdx.x;   // 0..TOTAL-1
    int b = slot >> 13;
    float4 q = g_sorted_adv[slot];
    int orig = g_adv_orig[slot];
    const float4* __restrict__ ob = g_sorted_ori + b * NPTS;
    const int* __restrict__ cntb = g_cnt_ori + b * NC;
    const int* __restrict__ offb = g_off_ori + b * NC;

    const float qx = q.x, qy = q.y, qz = q.z, ra = q.w;
    const int cx = cell1(qx), cy = cell1(qy), cz = cell1(qz);
    float best = 3.4e38f;   // current best squared distance

    for (int r = 0; r < G; r++) {
        int x0 = max(cx - r, 0), x1 = min(cx + r, G - 1);
        int y0 = max(cy - r, 0), y1 = min(cy + r, G - 1);
        int z0 = max(cz - r, 0), z1 = min(cz + r, G - 1);
        for (int iz = z0; iz <= z1; iz++) {
            int adz = abs(iz - cz);
            float lz = GRID_LO + iz * CELL_H;
            float bz = fmaxf(fmaxf(lz - qz, qz - (lz + CELL_H)), 0.0f);
            for (int iy = y0; iy <= y1; iy++) {
                int ady = abs(iy - cy);
                float ly = GRID_LO + iy * CELL_H;
                float by = fmaxf(fmaxf(ly - qy, qy - (ly + CELL_H)), 0.0f);
                float bzy = bz * bz + by * by;
                if (bzy >= best) continue;            // whole row can't improve
                bool shell_zy = (adz == r) || (ady == r);
                for (int ix = x0; ix <= x1; ix++) {
                    if (!shell_zy && abs(ix - cx) != r) continue;  // interior: done in earlier ring
                    int ci = (iz * G + iy) * G + ix;
                    int cnt = cntb[ci];
                    if (!cnt) continue;
                    float lx = GRID_LO + ix * CELL_H;
                    float bx = fmaxf(fmaxf(lx - qx, qx - (lx + CELL_H)), 0.0f);
                    float bd2 = bzy + bx * bx;
                    if (bd2 >= best) continue;        // cell can't improve
                    int o0 = offb[ci], oe = o0 + cnt;
                    for (int j = o0; j < oe; j++) {
                        float4 o = __ldg(ob + j);
                        float v = fmaf(-qx, o.x, fmaf(-qy, o.y, fmaf(-qz, o.z, o.w)));
                        best = fminf(best, fmaf(2.0f, v, ra));
                    }
                }
            }
        }
        // Lower bound on any point in a not-yet-searched cell: distance from q
        // to the nearest face of the searched index box that still has cells
        // beyond it. Monotone in r, so this termination is exact.
        float dn = 3.4e38f;
        if (cx - r > 0)     dn = fminf(dn, qx - (GRID_LO + (cx - r) * CELL_H));
        if (cx + r < G - 1) dn = fminf(dn, (GRID_LO + (cx + r + 1) * CELL_H) - qx);
        if (cy - r > 0)     dn = fminf(dn, qy - (GRID_LO + (cy - r) * CELL_H));
        if (cy + r < G - 1) dn = fminf(dn, (GRID_LO + (cy + r + 1) * CELL_H) - qy);
        if (cz - r > 0)     dn = fminf(dn, qz - (GRID_LO + (cz - r) * CELL_H));
        if (cz + r < G - 1) dn = fminf(dn, (GRID_LO + (cz + r + 1) * CELL_H) - qz);
        if (best <= dn * dn) break;   // dn==huge => whole grid searched => break
    }
    g_res[b * NPTS + orig] = best;
}

// ---------------------------------------------------------------- reduce
// One block, fixed strided assignment + fixed tree: bit-deterministic.
__global__ void k_reduce(const float* __restrict__ weights, float* __restrict__ out) {
    __shared__ float s[1024];
    int t = threadIdx.x;
    float sum = 0.0f;
    for (int i = t; i < TOTAL; i += 1024)
        sum += g_res[i] * __ldg(&weights[i >> 13]);
    s[t] = sum;
    __syncthreads();
    for (int d = 512; d > 0; d >>= 1) {
        if (t < d) s[t] += s[t + d];
        __syncthreads();
    }
    if (t == 0) out[0] = s[0] * (1.0f / (float)TOTAL);
}

extern "C" void kernel_launch(void* const* d_in, const int* in_sizes, int n_in,
                              void* d_out, int out_size) {
    const float* adv     = (const float*)d_in[0];  // adv_pc  [B, N, 3]  (queries)
    const float* ori     = (const float*)d_in[1];  // ori_pc  [B, N, 3]  (targets)
    const float* weights = (const float*)d_in[2];  // weights [B]
    float* out = (float*)d_out;                    // scalar

    k_zero   <<<256, 256>>>();
    k_count  <<<512, 256>>>(ori, adv);
    k_scan   <<<16, 1024>>>();
    k_scatter<<<512, 256>>>(ori, adv);
    k_query  <<<TOTAL / 128, 128>>>();
    k_reduce <<<1, 1024>>>(weights, out);
}

// round 9
// speedup vs baseline: 1.7127x; 1.7127x over previous
#include <cuda_runtime.h>
#include <math.h>

// Problem constants (fixed by the reference: B=8, N=8192, D=3)
#define BATCH   8
#define NPTS    8192
#define TOTAL   (BATCH * NPTS)        // 65536
#define G       32                    // grid cells per axis
#define NC      (G * G * G)           // 32768 cells per batch (2^15)
#define GRID_LO (-4.5f)
#define CELL_H  (0.28125f)            // 9.0 / 32
#define INV_H   (1.0f / CELL_H)
#define F_INF   __int_as_float(0x7f800000)

// Static scratch (no device allocation allowed).
__device__ int    g_cnt_ori[BATCH * NC];
__device__ int    g_off_ori[BATCH * NC];
__device__ int    g_cur_ori[BATCH * NC];
__device__ int    g_cnt_adv[BATCH * NC];
__device__ int    g_off_adv[BATCH * NC];
__device__ int    g_cur_adv[BATCH * NC];
__device__ float4 g_sorted_ori[TOTAL];   // (x, y, z, 0.5*||o||^2)
__device__ float4 g_sorted_adv[TOTAL];   // (x, y, z, ||a||^2)
__device__ int    g_adv_orig[TOTAL];     // original index within batch
__device__ float  g_res[TOTAL];          // per-query nearest dist^2, original order
__device__ int    g_fb_cnt;              // flagged-query count
__device__ int    g_fb_list[TOTAL];      // flagged GLOBAL sorted-slot indices

__device__ __forceinline__ int cell1(float v) {
    int c = (int)floorf((v - GRID_LO) * INV_H);
    return min(G - 1, max(0, c));
}

// ---------------------------------------------------------------- zero
__global__ void k_zero() {
    int i = blockIdx.x * blockDim.x + threadIdx.x;
    int stride = gridDim.x * blockDim.x;
    for (; i < BATCH * NC; i += stride) { g_cnt_ori[i] = 0; g_cnt_adv[i] = 0; }
    if (blockIdx.x == 0 && threadIdx.x == 0) g_fb_cnt = 0;
}

// ---------------------------------------------------------------- count
__global__ void k_count(const float* __restrict__ ori, const float* __restrict__ adv) {
    int t = blockIdx.x * blockDim.x + threadIdx.x;
    bool is_ori = t < TOTAL;
    int idx = is_ori ? t : t - TOTAL;
    int b = idx >> 13, i = idx & (NPTS - 1);
    const float* p = (is_ori ? ori : adv) + ((size_t)b * NPTS + i) * 3;
    int ci = (cell1(p[2]) * G + cell1(p[1])) * G + cell1(p[0]);
    atomicAdd((is_ori ? g_cnt_ori : g_cnt_adv) + b * NC + ci, 1);
}

// ---------------------------------------------------------------- scan
// 16 blocks: blockIdx 0..7 = ori batch b, 8..15 = adv batch b. 1024 threads.
// Offsets are batch-local (0..NPTS).
__global__ void k_scan() {
    __shared__ int s[1024];
    int kind = blockIdx.x >> 3, b = blockIdx.x & 7, t = threadIdx.x;
    int* cnt = (kind ? g_cnt_adv : g_cnt_ori) + b * NC;
    int* off = (kind ? g_off_adv : g_off_ori) + b * NC;
    int* cur = (kind ? g_cur_adv : g_cur_ori) + b * NC;
    const int CH = NC / 1024;   // 32 cells per thread
    int base = t * CH;
    int local = 0;
#pragma unroll
    for (int j = 0; j < CH; j++) local += cnt[base + j];
    s[t] = local;
    __syncthreads();
    for (int d = 1; d < 1024; d <<= 1) {
        int v = (t >= d) ? s[t - d] : 0;
        __syncthreads();
        s[t] += v;
        __syncthreads();
    }
    int run = s[t] - local;
    for (int j = 0; j < CH; j++) {
        off[base + j] = run;
        cur[base + j] = run;
        run += cnt[base + j];
    }
}

// ---------------------------------------------------------------- scatter
__global__ void k_scatter(const float* __restrict__ ori, const float* __restrict__ adv) {
    int t = blockIdx.x * blockDim.x + threadIdx.x;
    bool is_ori = t < TOTAL;
    int idx = is_ori ? t : t - TOTAL;
    int b = idx >> 13, i = idx & (NPTS - 1);
    const float* p = (is_ori ? ori : adv) + ((size_t)b * NPTS + i) * 3;
    float x = p[0], y = p[1], z = p[2];
    int ci = (cell1(z) * G + cell1(y)) * G + cell1(x);
    if (is_ori) {
        int pos = atomicAdd(&g_cur_ori[b * NC + ci], 1);
        g_sorted_ori[b * NPTS + pos] = make_float4(x, y, z, 0.5f * (x * x + y * y + z * z));
    } else {
        int pos = atomicAdd(&g_cur_adv[b * NC + ci], 1);
        g_sorted_adv[b * NPTS + pos] = make_float4(x, y, z, x * x + y * y + z * z);
        g_adv_orig[b * NPTS + pos] = i;
    }
}

// ---------------------------------------------------------------- query (warp per cell)
// One warp owns one (batch, cell). Lanes parallel over candidate ori points of
// the 3x3x3 neighborhood; all queries of the cell held in registers by every
// lane. Warp-uniform control flow; straight-line FFMA inner loop.
// NOTE: all slot indices here are GLOBAL (b*NPTS + batch-local position).
template <int QW>
__device__ __forceinline__ void cell_queries(int b, int qoff, int qcnt,
                                             int x0, int x1, int y0, int y1, int z0, int z1) {
    const int lane = threadIdx.x & 31;
    const float4* __restrict__ so = g_sorted_ori + b * NPTS;
    const float4* __restrict__ sa = g_sorted_adv + b * NPTS;
    const int* __restrict__ cnto = g_cnt_ori + b * NC;
    const int* __restrict__ offo = g_off_ori + b * NC;

    for (int qbase = 0; qbase < qcnt; qbase += QW) {
        const int nq = min(QW, qcnt - qbase);
        float qx[QW], qy[QW], qz[QW], qra[QW], qmin[QW];
#pragma unroll
        for (int k = 0; k < QW; k++) {
            float4 qv = (k < nq) ? sa[qoff + qbase + k] : make_float4(0.f, 0.f, 0.f, 0.f);
            qx[k] = qv.x; qy[k] = qv.y; qz[k] = qv.z; qra[k] = qv.w;
            qmin[k] = F_INF;
        }
        for (int iz = z0; iz <= z1; iz++)
            for (int iy = y0; iy <= y1; iy++)
                for (int ix = x0; ix <= x1; ix++) {
                    const int nci = (iz * G + iy) * G + ix;
                    const int ccnt = cnto[nci];
                    if (!ccnt) continue;
                    const int coff = offo[nci];
                    for (int cb = 0; cb < ccnt; cb += 32) {
                        const int j = cb + lane;
                        float4 o = (j < ccnt) ? __ldg(so + coff + j)
                                              : make_float4(0.f, 0.f, 0.f, F_INF);
#pragma unroll
                        for (int k = 0; k < QW; k++) {
                            float v = fmaf(-qx[k], o.x, fmaf(-qy[k], o.y, fmaf(-qz[k], o.z, o.w)));
                            qmin[k] = fminf(qmin[k], fmaf(2.0f, v, qra[k]));
                        }
                    }
                }
#pragma unroll
        for (int k = 0; k < QW; k++) {
            if (k >= nq) break;   // nq is warp-uniform
            float m = qmin[k];
#pragma unroll
            for (int s = 16; s > 0; s >>= 1) m = fminf(m, __shfl_xor_sync(0xffffffffu, m, s));
            if (lane == 0) {
                const int gslot = b * NPTS + qoff + qbase + k;   // GLOBAL slot
                g_res[b * NPTS + g_adv_orig[gslot]] = m;
                // Lower bound on distance to anything outside the searched box.
                float dn = 3.4e38f;
                if (x0 > 0)     dn = fminf(dn, qx[k] - (GRID_LO + x0 * CELL_H));
                if (x1 < G - 1) dn = fminf(dn, (GRID_LO + (x1 + 1) * CELL_H) - qx[k]);
                if (y0 > 0)     dn = fminf(dn, qy[k] - (GRID_LO + y0 * CELL_H));
                if (y1 < G - 1) dn = fminf(dn, (GRID_LO + (y1 + 1) * CELL_H) - qy[k]);
                if (z0 > 0)     dn = fminf(dn, qz[k] - (GRID_LO + z0 * CELL_H));
                if (z1 < G - 1) dn = fminf(dn, (GRID_LO + (z1 + 1) * CELL_H) - qz[k]);
                if (!(m <= dn * dn)) {          // also catches m == +inf
                    int p = atomicAdd(&g_fb_cnt, 1);
                    g_fb_list[p] = gslot;
                }
            }
        }
    }
}

__global__ __launch_bounds__(256) void k_query_warp() {
    const int w = blockIdx.x * 8 + (threadIdx.x >> 5);   // 0 .. BATCH*NC-1
    const int b = w >> 15;                               // NC = 2^15
    const int ci = w & (NC - 1);
    const int qcnt = g_cnt_adv[b * NC + ci];
    if (qcnt == 0) return;
    const int qoff = g_off_adv[b * NC + ci];
    const int cx = ci & 31, cy = (ci >> 5) & 31, cz = ci >> 10;
    const int x0 = max(cx - 1, 0), x1 = min(cx + 1, G - 1);
    const int y0 = max(cy - 1, 0), y1 = min(cy + 1, G - 1);
    const int z0 = max(cz - 1, 0), z1 = min(cz + 1, G - 1);
    if (qcnt <= 2) cell_queries<2>(b, qoff, qcnt, x0, x1, y0, y1, z0, z1);
    else           cell_queries<8>(b, qoff, qcnt, x0, x1, y0, y1, z0, z1);
}

// ---------------------------------------------------------------- fallback (warp per flagged query)
// Expanding Chebyshev rings from r=2 (r<=1 already searched exactly). Lanes
// parallel over ring cells; warp-uniform termination via face-distance bound.
__global__ __launch_bounds__(256) void k_fallback() {
    const int nflag = g_fb_cnt;
    const int lane = threadIdx.x & 31;
    const int wglobal = blockIdx.x * 8 + (threadIdx.x >> 5);

    for (int f = wglobal; f < nflag; f += gridDim.x * 8) {
        const int gslot = g_fb_list[f];          // GLOBAL slot
        const int b = gslot >> 13;               // NPTS = 2^13
        const float4 q = g_sorted_adv[gslot];
        const int orig = g_adv_orig[gslot];
        const float4* __restrict__ so = g_sorted_ori + b * NPTS;
        const int* __restrict__ cnto = g_cnt_ori + b * NC;
        const int* __restrict__ offo = g_off_ori + b * NC;
        const float qx = q.x, qy = q.y, qz = q.z, ra = q.w;
        const int cx = cell1(qx), cy = cell1(qy), cz = cell1(qz);
        float best = g_res[b * NPTS + orig];   // phase-1 upper bound (min over 3x3x3)

        for (int r = 2; r < G; r++) {
            const int x0 = max(cx - r, 0), x1 = min(cx + r, G - 1);
            const int y0 = max(cy - r, 0), y1 = min(cy + r, G - 1);
            const int z0 = max(cz - r, 0), z1 = min(cz + r, G - 1);
            const int nxw = x1 - x0 + 1, nyw = y1 - y0 + 1, nzw = z1 - z0 + 1;
            const int tot = nxw * nyw * nzw;
            float m = F_INF;
            for (int t = lane; t < tot; t += 32) {
                const int ix = x0 + t % nxw;
                const int rem = t / nxw;
                const int iy = y0 + rem % nyw;
                const int iz = z0 + rem / nyw;
                // skip interior (searched at smaller r / in phase 1)
                if (abs(ix - cx) < r && abs(iy - cy) < r && abs(iz - cz) < r) continue;
                const int nci = (iz * G + iy) * G + ix;
                const int c = cnto[nci];
                const int o0 = offo[nci];
                for (int j = 0; j < c; j++) {
                    float4 o = __ldg(so + o0 + j);
                    float v = fmaf(-qx, o.x, fmaf(-qy, o.y, fmaf(-qz, o.z, o.w)));
                    m = fminf(m, fmaf(2.0f, v, ra));
                }
            }
#pragma unroll
            for (int s = 16; s > 0; s >>= 1) m = fminf(m, __shfl_xor_sync(0xffffffffu, m, s));
            best = fminf(best, m);
            // Termination: nothing outside searched box can beat best.
            float dn = 3.4e38f;
            if (x0 > 0)     dn = fminf(dn, qx - (GRID_LO + x0 * CELL_H));
            if (x1 < G - 1) dn = fminf(dn, (GRID_LO + (x1 + 1) * CELL_H) - qx);
            if (y0 > 0)     dn = fminf(dn, qy - (GRID_LO + y0 * CELL_H));
            if (y1 < G - 1) dn = fminf(dn, (GRID_LO + (y1 + 1) * CELL_H) - qy);
            if (z0 > 0)     dn = fminf(dn, qz - (GRID_LO + z0 * CELL_H));
            if (z1 < G - 1) dn = fminf(dn, (GRID_LO + (z1 + 1) * CELL_H) - qz);
            if (best <= dn * dn) break;   // dn==huge => whole grid searched
        }
        if (lane == 0) g_res[b * NPTS + orig] = best;
    }
}

// ---------------------------------------------------------------- reduce
// One block, fixed strided assignment + fixed tree: bit-deterministic.
__global__ void k_reduce(const float* __restrict__ weights, float* __restrict__ out) {
    __shared__ float s[1024];
    int t = threadIdx.x;
    float sum = 0.0f;
    for (int i = t; i < TOTAL; i += 1024)
        sum += g_res[i] * __ldg(&weights[i >> 13]);
    s[t] = sum;
    __syncthreads();
    for (int d = 512; d > 0; d >>= 1) {
        if (t < d) s[t] += s[t + d];
        __syncthreads();
    }
    if (t == 0) out[0] = s[0] * (1.0f / (float)TOTAL);
}

extern "C" void kernel_launch(void* const* d_in, const int* in_sizes, int n_in,
                              void* d_out, int out_size) {
    const float* adv     = (const float*)d_in[0];  // adv_pc  [B, N, 3]  (queries)
    const float* ori     = (const float*)d_in[1];  // ori_pc  [B, N, 3]  (targets)
    const float* weights = (const float*)d_in[2];  // weights [B]
    float* out = (float*)d_out;                    // scalar

    k_zero      <<<256, 256>>>();
    k_count     <<<512, 256>>>(ori, adv);
    k_scan      <<<16, 1024>>>();
    k_scatter   <<<512, 256>>>(ori, adv);
    k_query_warp<<<BATCH * NC / 8, 256>>>();
    k_fallback  <<<1024, 256>>>();
    k_reduce    <<<1, 1024>>>(weights, out);
}

// round 10
// speedup vs baseline: 2.2492x; 1.3132x over previous
#include <cuda_runtime.h>
#include <math.h>

// Problem constants (fixed by the reference: B=8, N=8192, D=3)
#define BATCH   8
#define NPTS    8192
#define TOTAL   (BATCH * NPTS)        // 65536
#define G       32                    // fine cells per axis (ori binning)
#define NC      (G * G * G)           // 32768 fine cells per batch
#define SG      16                    // supercells per axis (adv binning)
#define NSC     (SG * SG * SG)        // 4096 supercells per batch
#define GRID_LO (-4.5f)
#define CELL_H  (0.28125f)            // 9.0 / 32
#define INV_H   (1.0f / CELL_H)
#define F_INF   __int_as_float(0x7f800000)
#define CAP     2048                  // staged candidates per chunk (32 KB smem)

// Static scratch (no device allocation allowed).
__device__ int    g_cnt_ori[BATCH * NC];
__device__ int    g_off_ori[BATCH * NC];
__device__ int    g_cur_ori[BATCH * NC];
__device__ int    g_cnt_adv[BATCH * NSC];
__device__ int    g_off_adv[BATCH * NSC];
__device__ int    g_cur_adv[BATCH * NSC];
__device__ float4 g_sorted_ori[TOTAL];   // (x, y, z, 0.5*||o||^2)
__device__ float4 g_sorted_adv[TOTAL];   // (x, y, z, ||a||^2), binned by supercell
__device__ int    g_adv_orig[TOTAL];     // original index within batch
__device__ float  g_res[TOTAL];          // per-query nearest dist^2, original order
__device__ int    g_fb_cnt;              // flagged-query count
__device__ int    g_fb_list[TOTAL];      // flagged GLOBAL sorted-slot indices

__device__ __forceinline__ int cell1(float v) {
    int c = (int)floorf((v - GRID_LO) * INV_H);
    return min(G - 1, max(0, c));
}

// ---------------------------------------------------------------- zero
__global__ void k_zero() {
    int i = blockIdx.x * blockDim.x + threadIdx.x;
    int stride = gridDim.x * blockDim.x;
    for (; i < BATCH * NC; i += stride) g_cnt_ori[i] = 0;
    for (i = blockIdx.x * blockDim.x + threadIdx.x; i < BATCH * NSC; i += stride) g_cnt_adv[i] = 0;
    if (blockIdx.x == 0 && threadIdx.x == 0) g_fb_cnt = 0;
}

// ---------------------------------------------------------------- count
__global__ void k_count(const float* __restrict__ ori, const float* __restrict__ adv) {
    int t = blockIdx.x * blockDim.x + threadIdx.x;
    bool is_ori = t < TOTAL;
    int idx = is_ori ? t : t - TOTAL;
    int b = idx >> 13, i = idx & (NPTS - 1);
    const float* p = (is_ori ? ori : adv) + ((size_t)b * NPTS + i) * 3;
    int cx = cell1(p[0]), cy = cell1(p[1]), cz = cell1(p[2]);
    if (is_ori) {
        atomicAdd(g_cnt_ori + b * NC + (cz * G + cy) * G + cx, 1);
    } else {
        atomicAdd(g_cnt_adv + b * NSC + ((cz >> 1) * SG + (cy >> 1)) * SG + (cx >> 1), 1);
    }
}

// ---------------------------------------------------------------- scan
// Blocks 0..7: ori batches (NC cells). Blocks 8..15: adv batches (NSC cells).
// Offsets batch-local. 1024 threads.
__global__ void k_scan() {
    __shared__ int s[1024];
    int kind = blockIdx.x >> 3, b = blockIdx.x & 7, t = threadIdx.x;
    int* cnt = kind ? (g_cnt_adv + b * NSC) : (g_cnt_ori + b * NC);
    int* off = kind ? (g_off_adv + b * NSC) : (g_off_ori + b * NC);
    int* cur = kind ? (g_cur_adv + b * NSC) : (g_cur_ori + b * NC);
    const int CH = kind ? (NSC / 1024) : (NC / 1024);   // 4 or 32
    int base = t * CH;
    int local = 0;
    for (int j = 0; j < CH; j++) local += cnt[base + j];
    s[t] = local;
    __syncthreads();
    for (int d = 1; d < 1024; d <<= 1) {
        int v = (t >= d) ? s[t - d] : 0;
        __syncthreads();
        s[t] += v;
        __syncthreads();
    }
    int run = s[t] - local;
    for (int j = 0; j < CH; j++) {
        off[base + j] = run;
        cur[base + j] = run;
        run += cnt[base + j];
    }
}

// ---------------------------------------------------------------- scatter
__global__ void k_scatter(const float* __restrict__ ori, const float* __restrict__ adv) {
    int t = blockIdx.x * blockDim.x + threadIdx.x;
    bool is_ori = t < TOTAL;
    int idx = is_ori ? t : t - TOTAL;
    int b = idx >> 13, i = idx & (NPTS - 1);
    const float* p = (is_ori ? ori : adv) + ((size_t)b * NPTS + i) * 3;
    float x = p[0], y = p[1], z = p[2];
    int cx = cell1(x), cy = cell1(y), cz = cell1(z);
    if (is_ori) {
        int ci = (cz * G + cy) * G + cx;
        int pos = atomicAdd(&g_cur_ori[b * NC + ci], 1);
        g_sorted_ori[b * NPTS + pos] = make_float4(x, y, z, 0.5f * (x * x + y * y + z * z));
    } else {
        int sc = ((cz >> 1) * SG + (cy >> 1)) * SG + (cx >> 1);
        int pos = atomicAdd(&g_cur_adv[b * NSC + sc], 1);
        g_sorted_adv[b * NPTS + pos] = make_float4(x, y, z, x * x + y * y + z * z);
        g_adv_orig[b * NPTS + pos] = i;
    }
}

// ---------------------------------------------------------------- query (block per supercell)
// One 128-thread block per (batch, supercell). Candidates from the expanded
// window (supercell +-1 fine cell, up to 4x4x4 fine cells) staged in smem ONCE;
// each thread owns one query (wave loop for >128) and runs the brute-force
// inner loop over smem (broadcast LDS, conflict-free).
__global__ __launch_bounds__(128) void k_query_super() {
    __shared__ float4 s_cand[CAP];             // 32 KB
    __shared__ int s_coff[64], s_cstart[65];

    const int blk = blockIdx.x;                // 0 .. BATCH*NSC-1
    const int b = blk >> 12;                   // NSC = 2^12
    const int sc = blk & (NSC - 1);
    const int qcnt = g_cnt_adv[b * NSC + sc];
    if (qcnt == 0) return;
    const int qoff = g_off_adv[b * NSC + sc];
    const int tid = threadIdx.x;

    const int scx = sc & (SG - 1), scy = (sc >> 4) & (SG - 1), scz = sc >> 8;
    const int fx0 = max(2 * scx - 1, 0), fx1 = min(2 * scx + 2, G - 1);
    const int fy0 = max(2 * scy - 1, 0), fy1 = min(2 * scy + 2, G - 1);
    const int fz0 = max(2 * scz - 1, 0), fz1 = min(2 * scz + 2, G - 1);
    const int nwx = fx1 - fx0 + 1, nwy = fy1 - fy0 + 1, nwz = fz1 - fz0 + 1;
    const int ncells = nwx * nwy * nwz;        // <= 64

    const float4* __restrict__ so = g_sorted_ori + b * NPTS;
    const int* __restrict__ cnto = g_cnt_ori + b * NC;
    const int* __restrict__ offo = g_off_ori + b * NC;

    // Gather per-cell (off, cnt) for the window.
    if (tid < ncells) {
        const int ix = fx0 + tid % nwx;
        const int rem = tid / nwx;
        const int iy = fy0 + rem % nwy;
        const int iz = fz0 + rem / nwy;
        const int ci = (iz * G + iy) * G + ix;
        s_coff[tid] = offo[ci];
        s_cstart[tid] = cnto[ci];   // temporarily counts
    }
    __syncthreads();
    if (tid == 0) {                 // tiny serial exclusive scan (<= 64)
        int run = 0;
        for (int c = 0; c < ncells; c++) {
            int v = s_cstart[c];
            s_cstart[c] = run;
            run += v;
        }
        s_cstart[ncells] = run;
    }
    __syncthreads();
    const int T = s_cstart[ncells];

    // Window box bounds (for the exactness flag).
    const float wlx = GRID_LO + fx0 * CELL_H, whx = GRID_LO + (fx1 + 1) * CELL_H;
    const float wly = GRID_LO + fy0 * CELL_H, why = GRID_LO + (fy1 + 1) * CELL_H;
    const float wlz = GRID_LO + fz0 * CELL_H, whz = GRID_LO + (fz1 + 1) * CELL_H;

    for (int qwave = 0; qwave < qcnt; qwave += 128) {
        const int qidx = qwave + tid;
        const bool qvalid = qidx < qcnt;
        const int gslot = b * NPTS + qoff + qidx;
        float4 q = qvalid ? g_sorted_adv[gslot] : make_float4(0.f, 0.f, 0.f, 0.f);
        const float nqx = -q.x, nqy = -q.y, nqz = -q.z;
        float mn = F_INF;
        // Only warps that hold at least one valid query run the math loop.
        const bool warp_active = (qwave + (tid & ~31)) < qcnt;

        for (int base = 0; base < T; base += CAP) {
            const int n = min(CAP, T - base);
            // Stage chunk: thread copies candidates strided; cell found by
            // binary search over s_cstart (uniform-ish, <=7 steps).
            for (int j = tid; j < n; j += 128) {
                const int gidx = base + j;
                int lo = 0, hi = ncells;
                while (hi - lo > 1) {
                    const int mid = (lo + hi) >> 1;
                    if (s_cstart[mid] <= gidx) lo = mid; else hi = mid;
                }
                s_cand[j] = __ldg(so + s_coff[lo] + (gidx - s_cstart[lo]));
            }
            __syncthreads();
            if (warp_active) {
#pragma unroll 4
                for (int j = 0; j < n; j++) {
                    const float4 o = s_cand[j];   // broadcast LDS.128
                    const float v = fmaf(nqx, o.x, fmaf(nqy, o.y, fmaf(nqz, o.z, o.w)));
                    mn = fminf(mn, fmaf(2.0f, v, q.w));
                }
            }
            __syncthreads();
        }

        if (qvalid) {
            g_res[b * NPTS + g_adv_orig[gslot]] = mn;
            // Lower bound on distance to anything outside the searched window.
            float dn = 3.4e38f;
            if (fx0 > 0)     dn = fminf(dn, q.x - wlx);
            if (fx1 < G - 1) dn = fminf(dn, whx - q.x);
            if (fy0 > 0)     dn = fminf(dn, q.y - wly);
            if (fy1 < G - 1) dn = fminf(dn, why - q.y);
            if (fz0 > 0)     dn = fminf(dn, q.z - wlz);
            if (fz1 < G - 1) dn = fminf(dn, whz - q.z);
            if (!(mn <= dn * dn)) {            // also catches mn == +inf
                int p = atomicAdd(&g_fb_cnt, 1);
                g_fb_list[p] = gslot;
            }
        }
    }
}

// ---------------------------------------------------------------- fallback (warp per flagged query)
// Expanding Chebyshev rings from r=2 around the query's fine cell (r<=1 is
// guaranteed covered by the phase-1 window). Lanes parallel over ring cells.
__global__ __launch_bounds__(256) void k_fallback() {
    const int nflag = g_fb_cnt;
    const int lane = threadIdx.x & 31;
    const int wglobal = blockIdx.x * 8 + (threadIdx.x >> 5);

    for (int f = wglobal; f < nflag; f += gridDim.x * 8) {
        const int gslot = g_fb_list[f];
        const int b = gslot >> 13;             // NPTS = 2^13
        const float4 q = g_sorted_adv[gslot];
        const int orig = g_adv_orig[gslot];
        const float4* __restrict__ so = g_sorted_ori + b * NPTS;
        const int* __restrict__ cnto = g_cnt_ori + b * NC;
        const int* __restrict__ offo = g_off_ori + b * NC;
        const float qx = q.x, qy = q.y, qz = q.z, ra = q.w;
        const int cx = cell1(qx), cy = cell1(qy), cz = cell1(qz);
        float best = g_res[b * NPTS + orig];   // phase-1 upper bound

        for (int r = 2; r < G; r++) {
            const int x0 = max(cx - r, 0), x1 = min(cx + r, G - 1);
            const int y0 = max(cy - r, 0), y1 = min(cy + r, G - 1);
            const int z0 = max(cz - r, 0), z1 = min(cz + r, G - 1);
            const int nxw = x1 - x0 + 1, nyw = y1 - y0 + 1, nzw = z1 - z0 + 1;
            const int tot = nxw * nyw * nzw;
            float m = F_INF;
            for (int t = lane; t < tot; t += 32) {
                const int ix = x0 + t % nxw;
                const int rem = t / nxw;
                const int iy = y0 + rem % nyw;
                const int iz = z0 + rem / nyw;
                if (abs(ix - cx) < r && abs(iy - cy) < r && abs(iz - cz) < r) continue;
                const int nci = (iz * G + iy) * G + ix;
                const int c = cnto[nci];
                const int o0 = offo[nci];
                for (int j = 0; j < c; j++) {
                    float4 o = __ldg(so + o0 + j);
                    float v = fmaf(-qx, o.x, fmaf(-qy, o.y, fmaf(-qz, o.z, o.w)));
                    m = fminf(m, fmaf(2.0f, v, ra));
                }
            }
#pragma unroll
            for (int s = 16; s > 0; s >>= 1) m = fminf(m, __shfl_xor_sync(0xffffffffu, m, s));
            best = fminf(best, m);
            float dn = 3.4e38f;
            if (x0 > 0)     dn = fminf(dn, qx - (GRID_LO + x0 * CELL_H));
            if (x1 < G - 1) dn = fminf(dn, (GRID_LO + (x1 + 1) * CELL_H) - qx);
            if (y0 > 0)     dn = fminf(dn, qy - (GRID_LO + y0 * CELL_H));
            if (y1 < G - 1) dn = fminf(dn, (GRID_LO + (y1 + 1) * CELL_H) - qy);
            if (z0 > 0)     dn = fminf(dn, qz - (GRID_LO + z0 * CELL_H));
            if (z1 < G - 1) dn = fminf(dn, (GRID_LO + (z1 + 1) * CELL_H) - qz);
            if (best <= dn * dn) break;        // dn==huge => whole grid searched
        }
        if (lane == 0) g_res[b * NPTS + orig] = best;
    }
}

// ---------------------------------------------------------------- reduce
// One block, fixed strided assignment + fixed tree: bit-deterministic.
__global__ void k_reduce(const float* __restrict__ weights, float* __restrict__ out) {
    __shared__ float s[1024];
    int t = threadIdx.x;
    float sum = 0.0f;
    for (int i = t; i < TOTAL; i += 1024)
        sum += g_res[i] * __ldg(&weights[i >> 13]);
    s[t] = sum;
    __syncthreads();
    for (int d = 512; d > 0; d >>= 1) {
        if (t < d) s[t] += s[t + d];
        __syncthreads();
    }
    if (t == 0) out[0] = s[0] * (1.0f / (float)TOTAL);
}

extern "C" void kernel_launch(void* const* d_in, const int* in_sizes, int n_in,
                              void* d_out, int out_size) {
    const float* adv     = (const float*)d_in[0];  // adv_pc  [B, N, 3]  (queries)
    const float* ori     = (const float*)d_in[1];  // ori_pc  [B, N, 3]  (targets)
    const float* weights = (const float*)d_in[2];  // weights [B]
    float* out = (float*)d_out;                    // scalar

    k_zero       <<<256, 256>>>();
    k_count      <<<512, 256>>>(ori, adv);
    k_scan       <<<16, 1024>>>();
    k_scatter    <<<512, 256>>>(ori, adv);
    k_query_super<<<BATCH * NSC, 128>>>();
    k_fallback   <<<1024, 256>>>();
    k_reduce     <<<1, 1024>>>(weights, out);
}